// round 7
// baseline (speedup 1.0000x reference)
#include <cuda_runtime.h>

#define Bn 64
#define Tn 2048
#define In 128
#define Hn 256
#define THREADS 512
#define PT 256
#define NCOL 16                 // columns per CTA
#define NBAT 8                  // batches per CTA
#define NCG  (Hn / NCOL)        // 16 col-groups
#define NBG  (Bn / NBAT)        // 8 batch-groups
#define GCTA (NCG * NBG)        // 128 CTAs
#define KA 384
#define KB 512
#define RSTRIDE 10

typedef unsigned long long u64;

// ---------------- device scratch (static; no allocations) ----------------
__device__ __align__(256) u64   g_xT2[(size_t)Tn * In * Bn];  // x dup'd {v,v}: [t][k][b]
__device__ __align__(256) float g_h0[2 * Hn * Bn];            // plain fp32, [buf][k][b]
__device__ __align__(256) float g_h1[2 * Hn * Bn];
__device__ unsigned g_count;

// ---------------- packed f32x2 helpers ----------------
__device__ __forceinline__ void fma2(u64 &d, u64 a, u64 b) {
    asm("fma.rn.f32x2 %0, %1, %2, %0;" : "+l"(d) : "l"(a), "l"(b));
}
__device__ __forceinline__ u64 add2(u64 a, u64 b) {
    u64 d; asm("add.rn.f32x2 %0, %1, %2;" : "=l"(d) : "l"(a), "l"(b)); return d;
}
__device__ __forceinline__ u64 dup2(float f) {
    u64 d; asm("mov.b64 %0, {%1, %1};" : "=l"(d) : "f"(f)); return d;
}
__device__ __forceinline__ u64 pack2(float lo, float hi) {
    u64 d; asm("mov.b64 %0, {%1, %2};" : "=l"(d) : "f"(lo), "f"(hi)); return d;
}
__device__ __forceinline__ float lo2(u64 v) { return __uint_as_float((unsigned)(v & 0xffffffffull)); }
__device__ __forceinline__ float hi2(u64 v) { return __uint_as_float((unsigned)(v >> 32)); }

// L2-coherent accesses (state crosses SMs every step)
__device__ __forceinline__ void ldcg2(const u64* p, u64 &a, u64 &b) {
    asm volatile("ld.global.cg.v2.u64 {%0, %1}, [%2];" : "=l"(a), "=l"(b) : "l"(p));
}
__device__ __forceinline__ float4 ldcgf4(const float* p) {
    float4 v;
    asm volatile("ld.global.cg.v4.f32 {%0, %1, %2, %3}, [%4];"
                 : "=f"(v.x), "=f"(v.y), "=f"(v.z), "=f"(v.w) : "l"(p));
    return v;
}
__device__ __forceinline__ void stcgf(float* p, float v) {
    asm volatile("st.global.cg.f32 [%0], %1;" :: "l"(p), "f"(v) : "memory");
}

// ---------------- grid barrier (release/acquire, no membar) ----------------
__device__ __forceinline__ void grid_barrier(unsigned target) {
    __syncthreads();
    if (threadIdx.x == 0) {
        unsigned old;
        asm volatile("atom.release.gpu.global.add.u32 %0, [%1], 1;"
                     : "=r"(old) : "l"(&g_count) : "memory");
        unsigned v;
        do {
            asm volatile("ld.acquire.gpu.global.u32 %0, [%1];"
                         : "=r"(v) : "l"(&g_count) : "memory");
        } while (v < target);
    }
    __syncthreads();
}

// ---------------- prep: transpose + dup x, zero states, reset barrier ----------------
__global__ void prep_kernel(const float* __restrict__ x) {
    __shared__ float s[In][65];
    const int t = blockIdx.x;
    const int tid = threadIdx.x;
    for (int idx = tid; idx < Bn * In; idx += PT) {
        int b = idx >> 7, i = idx & (In - 1);
        s[i][b] = x[((size_t)b * Tn + t) * In + i];
    }
    __syncthreads();
    for (int idx = tid; idx < In * Bn; idx += PT) {
        int i = idx >> 6, b = idx & (Bn - 1);
        g_xT2[((size_t)t * In + i) * Bn + b] = dup2(s[i][b]);
    }
    if (t == 0 && tid == 0) g_count = 0u;
    if (t < 2) {
        for (int i = tid; i < Hn * Bn; i += PT) {
            g_h0[t * Hn * Bn + i] = 0.0f;
            g_h1[t * Hn * Bn + i] = 0.0f;
        }
    }
}

// ---------------- persistent RNN kernel ----------------
__global__ void __launch_bounds__(THREADS, 1) rnn_kernel(
    const float* __restrict__ Wih0, const float* __restrict__ Whh0,
    const float* __restrict__ bh0,  const float* __restrict__ Wax0,
    const float* __restrict__ Wah0, const float* __restrict__ ba0,
    const float* __restrict__ Wih1, const float* __restrict__ Whh1,
    const float* __restrict__ bh1,  const float* __restrict__ Wax1,
    const float* __restrict__ Wah1, const float* __restrict__ ba1,
    float* __restrict__ out)
{
    extern __shared__ u64 sm[];
    u64* wAs   = sm;                        // [KA][16] (wc,wa) pairs
    u64* wBs   = wAs + KA * NCOL;           // [KB][16]
    u64* sh0   = wBs + KB * NCOL;           // [Hn][NBAT] dup'd state h0[t]
    u64* sh1   = sh0 + Hn * NBAT;           // [Hn][NBAT] dup'd state h1[t-1]
    u64* red   = sh1 + Hn * NBAT;           // [512][RSTRIDE]
    u64* sbias = red + THREADS * RSTRIDE;   // [2][16]

    const int tid  = threadIdx.x;
    const int cg   = blockIdx.x & (NCG - 1);
    const int bg   = blockIdx.x >> 4;
    const int col0 = cg * NCOL;
    const int b0g  = bg * NBAT;

    // ---- one-time weight gather: (wc, wa) packed per col per k ----
    for (int idx = tid; idx < KA * NCOL; idx += THREADS) {
        int k = idx >> 4, c = idx & 15, C = col0 + c;
        float wc = (k < In) ? Wih0[k * Hn + C] : Whh0[(k - In) * Hn + C];
        float wa = (k < In) ? Wax0[k * Hn + C] : Wah0[(k - In) * Hn + C];
        wAs[idx] = pack2(wc, wa);
    }
    for (int idx = tid; idx < KB * NCOL; idx += THREADS) {
        int k = idx >> 4, c = idx & 15, C = col0 + c;
        float wc = (k < Hn) ? Wih1[k * Hn + C] : Whh1[(k - Hn) * Hn + C];
        float wa = (k < Hn) ? Wax1[k * Hn + C] : Wah1[(k - Hn) * Hn + C];
        wBs[idx] = pack2(wc, wa);
    }
    if (tid < 2 * NCOL) {
        int c = tid & 15, l = tid >> 4;
        sbias[tid] = l ? pack2(bh1[col0 + c], ba1[col0 + c])
                       : pack2(bh0[col0 + c], ba0[col0 + c]);
    }
    __syncthreads();

    // ---- accumulation mapping: 16 warps = K-slices; lane = (batch-pair, col-pair) ----
    const int w  = tid >> 5;
    const int ln = tid & 31;
    const int bp = ln >> 3;
    const int cp = ln & 7;
    const int b0 = b0g + bp * 2;
    const int kx = w * 8;
    const int kh = w * 16;

    // ---- staging mapping: thread -> (k, batch-half) float4 ----
    const int sk = tid >> 1;
    const int sb = (tid & 1) * 4;

    // ---- epilogue mapping (tid < 256) ----
    const int rp   = tid >> 7;
    const int cell = tid & 127;
    const int rb   = cell >> 4;
    const int rc   = cell & 15;
    const int ridx = (rb >> 1) * 8 + (rc >> 1);
    const int raid = rp * 4 + (rb & 1) * 2 + (rc & 1);
    float hprev = 0.0f;

    // x-part prefetch (no barrier dependence)
    auto xpart = [&](int s, u64 &a00, u64 &a01, u64 &a10, u64 &a11) {
        const u64* xp = g_xT2 + ((size_t)s * In + kx) * Bn + b0;
        const u64* wp = wAs + kx * NCOL + cp * 2;
#pragma unroll
        for (int k = 0; k < 8; k++) {
            u64 s0, s1; ldcg2(xp + (size_t)k * Bn, s0, s1);
            ulonglong2 wv = *(const ulonglong2*)(wp + k * NCOL);
            fma2(a00, s0, wv.x); fma2(a01, s0, wv.y);
            fma2(a10, s1, wv.x); fma2(a11, s1, wv.y);
        }
    };

    u64 x00 = 0, x01 = 0, x10 = 0, x11 = 0;
    xpart(0, x00, x01, x10, x11);

    unsigned bar = 1;

    // iteration t: phase B -> h1[t] (t>=0); phase A -> h0[t+1] (t+1<Tn)
    for (int t = -1; t < Tn; t++) {
        const int s = t + 1;
        const bool doA = (s < Tn);
        const bool doB = (t >= 0);

        // -- stage h0[t], h1[t-1] into SMEM (coalesced, dedup'd source) --
        {
            float4 v0 = ldcgf4(&g_h0[((t & 1) * Hn + sk) * Bn + b0g + sb]);
            float4 v1 = ldcgf4(&g_h1[((((t + 1) & 1)) * Hn + sk) * Bn + b0g + sb]);
            u64* d0 = sh0 + sk * NBAT + sb;
            u64* d1 = sh1 + sk * NBAT + sb;
            d0[0] = dup2(v0.x); d0[1] = dup2(v0.y); d0[2] = dup2(v0.z); d0[3] = dup2(v0.w);
            d1[0] = dup2(v1.x); d1[1] = dup2(v1.y); d1[2] = dup2(v1.z); d1[3] = dup2(v1.w);
        }
        __syncthreads();

        u64 aA00 = x00, aA01 = x01, aA10 = x10, aA11 = x11;
        u64 aB00 = 0, aB01 = 0, aB10 = 0, aB11 = 0;

        // -- shared h0[t] part from SMEM: feeds A (Whh0/Wah0) and B (Wih1/Wax1) --
        {
            const u64* hp  = sh0 + kh * NBAT + bp * 2;
            const u64* wpa = wAs + (In + kh) * NCOL + cp * 2;
            const u64* wpb = wBs + kh * NCOL + cp * 2;
            if (doA && doB) {
#pragma unroll 8
                for (int k = 0; k < 16; k++) {
                    ulonglong2 sv = *(const ulonglong2*)(hp + k * NBAT);
                    ulonglong2 wa = *(const ulonglong2*)(wpa + k * NCOL);
                    ulonglong2 wb = *(const ulonglong2*)(wpb + k * NCOL);
                    fma2(aA00, sv.x, wa.x); fma2(aA01, sv.x, wa.y);
                    fma2(aA10, sv.y, wa.x); fma2(aA11, sv.y, wa.y);
                    fma2(aB00, sv.x, wb.x); fma2(aB01, sv.x, wb.y);
                    fma2(aB10, sv.y, wb.x); fma2(aB11, sv.y, wb.y);
                }
            } else if (doA) {
#pragma unroll 8
                for (int k = 0; k < 16; k++) {
                    ulonglong2 sv = *(const ulonglong2*)(hp + k * NBAT);
                    ulonglong2 wa = *(const ulonglong2*)(wpa + k * NCOL);
                    fma2(aA00, sv.x, wa.x); fma2(aA01, sv.x, wa.y);
                    fma2(aA10, sv.y, wa.x); fma2(aA11, sv.y, wa.y);
                }
            } else {
#pragma unroll 8
                for (int k = 0; k < 16; k++) {
                    ulonglong2 sv = *(const ulonglong2*)(hp + k * NBAT);
                    ulonglong2 wb = *(const ulonglong2*)(wpb + k * NCOL);
                    fma2(aB00, sv.x, wb.x); fma2(aB01, sv.x, wb.y);
                    fma2(aB10, sv.y, wb.x); fma2(aB11, sv.y, wb.y);
                }
            }
        }

        // -- h1[t-1] part (B) from SMEM --
        if (doB) {
            const u64* hp = sh1 + kh * NBAT + bp * 2;
            const u64* wp = wBs + (Hn + kh) * NCOL + cp * 2;
#pragma unroll 8
            for (int k = 0; k < 16; k++) {
                ulonglong2 sv = *(const ulonglong2*)(hp + k * NBAT);
                ulonglong2 wv = *(const ulonglong2*)(wp + k * NCOL);
                fma2(aB00, sv.x, wv.x); fma2(aB01, sv.x, wv.y);
                fma2(aB10, sv.y, wv.x); fma2(aB11, sv.y, wv.y);
            }
        }

        // -- stage partials --
        {
            u64* rr = red + tid * RSTRIDE;
            *(ulonglong2*)(rr + 0) = make_ulonglong2(aA00, aA01);
            *(ulonglong2*)(rr + 2) = make_ulonglong2(aA10, aA11);
            *(ulonglong2*)(rr + 4) = make_ulonglong2(aB00, aB01);
            *(ulonglong2*)(rr + 6) = make_ulonglong2(aB10, aB11);
        }
        __syncthreads();

        // -- reduce + epilogue (tid<256); others go prefetch x --
        if (tid < 256 && (rp ? doB : doA)) {
            u64 acc0 = sbias[rp * NCOL + rc];
            u64 acc1 = 0;
#pragma unroll
            for (int ww = 0; ww < 16; ww += 2) {
                acc0 = add2(acc0, red[(ww * 32 + ridx) * RSTRIDE + raid]);
                acc1 = add2(acc1, red[((ww + 1) * 32 + ridx) * RSTRIDE + raid]);
            }
            u64 acc = add2(acc0, acc1);
            float cnd = lo2(acc), alp = hi2(acc);
            float tv = 1.0f - __fdividef(2.0f, __expf(2.0f * cnd) + 1.0f);
            float sg = __fdividef(1.0f, 1.0f + __expf(-alp));
            float hn = fmaf(sg, tv - hprev, hprev);
            hprev = hn;
            const int C = col0 + rc, B = b0g + rb;
            if (rp == 0) {
                stcgf(&g_h0[((s & 1) * Hn + C) * Bn + B], hn);
            } else {
                stcgf(&g_h1[((t & 1) * Hn + C) * Bn + B], hn);
                out[((size_t)B * Tn + t) * Hn + C] = hn;
            }
        }

        // -- prefetch x-part for step t+2 (fills barrier window) --
        x00 = 0; x01 = 0; x10 = 0; x11 = 0;
        if (t + 2 < Tn) xpart(t + 2, x00, x01, x10, x11);

        grid_barrier(GCTA * bar); bar++;
    }

    // ---- h_final: [2][B][H] appended after outputs ----
    if (tid < 256) {
        const int l = tid >> 7, r = tid & 127;
        const int b = r >> 4, c = r & 15;
        const int C = col0 + c, B = b0g + b;
        const float* src = l ? &g_h1[(1 * Hn + C) * Bn + B]
                             : &g_h0[(1 * Hn + C) * Bn + B];   // (Tn-1)&1 == 1
        out[(size_t)Bn * Tn * Hn + (size_t)l * Bn * Hn + (size_t)B * Hn + C] = *src;
    }
}

// ---------------- launch ----------------
extern "C" void kernel_launch(void* const* d_in, const int* in_sizes, int n_in,
                              void* d_out, int out_size) {
    const float* x    = (const float*)d_in[0];
    const float* Wih0 = (const float*)d_in[1];
    const float* Whh0 = (const float*)d_in[2];
    const float* bh0  = (const float*)d_in[3];
    const float* Wax0 = (const float*)d_in[4];
    const float* Wah0 = (const float*)d_in[5];
    const float* ba0  = (const float*)d_in[6];
    const float* Wih1 = (const float*)d_in[7];
    const float* Whh1 = (const float*)d_in[8];
    const float* bh1  = (const float*)d_in[9];
    const float* Wax1 = (const float*)d_in[10];
    const float* Wah1 = (const float*)d_in[11];
    const float* ba1  = (const float*)d_in[12];
    float* out = (float*)d_out;

    const int smem = (KA + KB) * NCOL * 8        // weights
                   + 2 * Hn * NBAT * 8           // sh0 + sh1
                   + THREADS * RSTRIDE * 8       // red
                   + 2 * NCOL * 8;               // bias
    cudaFuncSetAttribute(rnn_kernel, cudaFuncAttributeMaxDynamicSharedMemorySize, smem);

    prep_kernel<<<Tn, PT>>>(x);
    rnn_kernel<<<GCTA, THREADS, smem>>>(
        Wih0, Whh0, bh0, Wax0, Wah0, ba0,
        Wih1, Whh1, bh1, Wax1, Wah1, ba1,
        out);
}